// round 5
// baseline (speedup 1.0000x reference)
#include <cuda_runtime.h>

#define BATCH 128
#define NIN   1024
#define NOUT  512
#define JT    32
#define NJT   (NOUT / JT)   // 16
#define NCH   37            // 36 chunks of 28 + 1 of 16
#define PITCH 132           // padded b-stride (132%32==4 -> low STS conflicts)
#define E0    2.1245f
#define LN2   0.69314718f

typedef unsigned long long u64;

__device__ int   g_max_bits;                       // zero-init; monotone -> replay-stable
__device__ float g_partial[NCH * BATCH * NOUT];    // 9.7 MB

__device__ __forceinline__ float ex2f_(float x) {
    float y; asm("ex2.approx.f32 %0, %1;" : "=f"(y) : "f"(x)); return y;
}
__device__ __forceinline__ float lg2f_(float x) {
    float y; asm("lg2.approx.f32 %0, %1;" : "=f"(y) : "f"(x)); return y;
}
__device__ __forceinline__ u64 pk2(float lo, float hi) {
    u64 r; asm("mov.b64 %0, {%1, %2};" : "=l"(r) : "f"(lo), "f"(hi)); return r;
}
__device__ __forceinline__ u64 fma2_(u64 a, u64 b, u64 c) {
    u64 d; asm("fma.rn.f32x2 %0, %1, %2, %3;" : "=l"(d) : "l"(a), "l"(b), "l"(c)); return d;
}

// ---------------------------------------------------------------------------
// Kernel 1: max |w|, MLP=4 per thread, 256 blocks.
// ---------------------------------------------------------------------------
__global__ void __launch_bounds__(256, 8)
k_max(const float4* __restrict__ wp4, const float4* __restrict__ wn4) {
    const int gid = blockIdx.x * blockDim.x + threadIdx.x;   // 65536 threads
    float4 a0 = wp4[gid], a1 = wp4[gid + 65536];
    float4 b0 = wn4[gid], b1 = wn4[gid + 65536];
    float m = 0.5f;
    m = fmaxf(m, fmaxf(fmaxf(fabsf(a0.x), fabsf(a0.y)), fmaxf(fabsf(a0.z), fabsf(a0.w))));
    m = fmaxf(m, fmaxf(fmaxf(fabsf(a1.x), fabsf(a1.y)), fmaxf(fabsf(a1.z), fabsf(a1.w))));
    m = fmaxf(m, fmaxf(fmaxf(fabsf(b0.x), fabsf(b0.y)), fmaxf(fabsf(b0.z), fabsf(b0.w))));
    m = fmaxf(m, fmaxf(fmaxf(fabsf(b1.x), fabsf(b1.y)), fmaxf(fabsf(b1.z), fabsf(b1.w))));
    #pragma unroll
    for (int o = 16; o; o >>= 1) m = fmaxf(m, __shfl_xor_sync(0xffffffffu, m, o));
    __shared__ float sm[8];
    const int lane = threadIdx.x & 31, w = threadIdx.x >> 5;
    if (lane == 0) sm[w] = m;
    __syncthreads();
    if (threadIdx.x == 0) {
        #pragma unroll
        for (int i = 1; i < 8; i++) m = fmaxf(m, sm[i]);
        atomicMax(&g_max_bits, __float_as_int(m));
    }
}

// ---------------------------------------------------------------------------
// Kernel 2: main compute, MUFU-free inner loop (separable Taylor, K=5).
//   term = sum_k phi_k[b,i] * C_k[i,j]
//   phi_k = vr^E0 * (lv*ln2)^k / k!     (staging, MUFU there only)
//   C_k   = cp*eps_p^k - cn*eps_n^k
// Inner loop: 5 fma2 per batch-pair -> 2.5 fma-issues/element, 0 MUFU.
// ---------------------------------------------------------------------------
#define PHI(ii, k, b) phi_s[(ii) * (5 * PITCH) + (k) * PITCH + (b)]

template<int ROWS>
__device__ __forceinline__ void compute_half(
    const float* __restrict__ x,
    const float* __restrict__ w_pos, const float* __restrict__ w_neg,
    const float* __restrict__ n_param,
    float* phi_s, float4* coefA, float* coefB,
    int i0, int j0, int tid, int jx, int bbase, float cG, u64* acc)
{
    // ---- stage phi[ii][k][b]
    constexpr int TOT_LV = ROWS * BATCH;
    #pragma unroll
    for (int r = 0; r < (TOT_LV + 255) / 256; r++) {
        int idx = r * 256 + tid;
        if ((TOT_LV % 256 == 0) || idx < TOT_LV) {
            int b  = idx / ROWS;
            int ii = idx - b * ROWS;
            float xv = fminf(fmaxf(x[b * NIN + i0 + ii], 0.0f), 1.0f);
            float lv = fmaxf(lg2f_(2.0f * xv), -8.0f);
            float p0 = ex2f_(E0 * lv);
            float L  = lv * LN2;
            float p1 = p0 * L;
            float p2 = p1 * (L * 0.5f);
            float p3 = p2 * (L * 0.333333333f);
            float p4 = p3 * (L * 0.25f);
            PHI(ii, 0, b) = p0;
            PHI(ii, 1, b) = p1;
            PHI(ii, 2, b) = p2;
            PHI(ii, 3, b) = p3;
            PHI(ii, 4, b) = p4;
        }
    }
    // ---- stage C_k[ii][jj]
    constexpr int TOT_CF = ROWS * JT;
    #pragma unroll
    for (int r = 0; r < (TOT_CF + 255) / 256; r++) {
        int idx = r * 256 + tid;
        if ((TOT_CF % 256 == 0) || idx < TOT_CF) {
            int ii = idx >> 5, jj = idx & 31;
            int i = i0 + ii, j = j0 + jj;
            float cp = 0.5f * (fabsf(w_pos[i * NOUT + j]) + cG);
            float cn = 0.5f * (fabsf(w_neg[i * NOUT + j]) + cG);
            float2 np = reinterpret_cast<const float2*>(n_param)[i * NOUT + j];
            float ep = lg2f_(np.x) + 1.0f - E0;    // eps_p
            float en = lg2f_(np.y) + 1.0f - E0;    // eps_n
            float ep2 = ep * ep, en2 = en * en;
            coefA[idx] = make_float4(cp - cn,
                                     cp * ep - cn * en,
                                     cp * ep2 - cn * en2,
                                     cp * ep2 * ep - cn * en2 * en);
            coefB[idx] = cp * ep2 * ep2 - cn * en2 * en2;
        }
    }
    __syncthreads();

    // ---- inner loop: pure FFMA2
    #pragma unroll 2
    for (int ii = 0; ii < ROWS; ii++) {
        float4 cA = coefA[ii * JT + jx];
        float  cB = coefB[ii * JT + jx];
        u64 Cp[5];
        Cp[0] = pk2(cA.x, cA.x); Cp[1] = pk2(cA.y, cA.y);
        Cp[2] = pk2(cA.z, cA.z); Cp[3] = pk2(cA.w, cA.w);
        Cp[4] = pk2(cB, cB);
        const float* base = &PHI(ii, 0, bbase);
        #pragma unroll
        for (int k = 0; k < 5; k++) {
            const ulonglong2* pr = reinterpret_cast<const ulonglong2*>(base + k * PITCH);
            ulonglong2 q0 = pr[0], q1 = pr[1], q2 = pr[2], q3 = pr[3];
            acc[0] = fma2_(Cp[k], q0.x, acc[0]);
            acc[1] = fma2_(Cp[k], q0.y, acc[1]);
            acc[2] = fma2_(Cp[k], q1.x, acc[2]);
            acc[3] = fma2_(Cp[k], q1.y, acc[3]);
            acc[4] = fma2_(Cp[k], q2.x, acc[4]);
            acc[5] = fma2_(Cp[k], q2.y, acc[5]);
            acc[6] = fma2_(Cp[k], q3.x, acc[6]);
            acc[7] = fma2_(Cp[k], q3.y, acc[7]);
        }
    }
    __syncthreads();
}

__global__ void __launch_bounds__(256)
k_main(const float* __restrict__ x,
       const float* __restrict__ w_pos, const float* __restrict__ w_neg,
       const float* __restrict__ n_param) {
    __shared__ __align__(16) float  phi_s[14 * 5 * PITCH];   // 36.96 KB
    __shared__ __align__(16) float4 coefA[14 * JT];          //  7.17 KB
    __shared__ __align__(16) float  coefB[14 * JT];          //  1.79 KB

    const int tid   = threadIdx.x;
    const int jx    = tid & 31;
    const int bbase = (tid >> 5) * 16;
    const int j0    = blockIdx.x * JT;
    const int ch    = blockIdx.y;
    const float cG  = __int_as_float(g_max_bits) * (1.0f / 9.0f);

    u64 acc[8];
    #pragma unroll
    for (int p = 0; p < 8; p++) acc[p] = 0ull;

    if (ch < 36) {
        int i0 = ch * 28;
        compute_half<14>(x, w_pos, w_neg, n_param, phi_s, coefA, coefB,
                         i0,      j0, tid, jx, bbase, cG, acc);
        compute_half<14>(x, w_pos, w_neg, n_param, phi_s, coefA, coefB,
                         i0 + 14, j0, tid, jx, bbase, cG, acc);
    } else {
        compute_half<8>(x, w_pos, w_neg, n_param, phi_s, coefA, coefB,
                        1008, j0, tid, jx, bbase, cG, acc);
        compute_half<8>(x, w_pos, w_neg, n_param, phi_s, coefA, coefB,
                        1016, j0, tid, jx, bbase, cG, acc);
    }

    float* outp = &g_partial[ch * (BATCH * NOUT)];
    #pragma unroll
    for (int p = 0; p < 8; p++) {
        float2 v; asm("mov.b64 {%0, %1}, %2;" : "=f"(v.x), "=f"(v.y) : "l"(acc[p]));
        outp[(bbase + 2 * p)     * NOUT + j0 + jx] = v.x;
        outp[(bbase + 2 * p + 1) * NOUT + j0 + jx] = v.y;
    }
}

// ---------------------------------------------------------------------------
// Kernel 3: deterministic reduction over chunks + exact bias term
// (bias row: vr = 2 exactly -> vr^(lg2 n + 1) = 2n -> term = (|b|+cG)*n)
// ---------------------------------------------------------------------------
__global__ void k_reduce(float4* __restrict__ out,
                         const float* __restrict__ b_pos,
                         const float* __restrict__ b_neg,
                         const float* __restrict__ n_param) {
    const int t = blockIdx.x * blockDim.x + threadIdx.x;   // 16384 threads
    const float4* gp = reinterpret_cast<const float4*>(g_partial);
    float4 s = make_float4(0.0f, 0.0f, 0.0f, 0.0f);
    #pragma unroll
    for (int c = 0; c < NCH; c++) {
        float4 v = gp[c * (BATCH * NOUT / 4) + t];
        s.x += v.x; s.y += v.y; s.z += v.z; s.w += v.w;
    }
    const int j = (t * 4) & (NOUT - 1);
    const float cG = __int_as_float(g_max_bits) * (1.0f / 9.0f);
    float4 bp = *reinterpret_cast<const float4*>(&b_pos[j]);
    float4 bn = *reinterpret_cast<const float4*>(&b_neg[j]);
    const float* nrow = n_param + (size_t)NIN * (2 * NOUT);
    float4 n0 = *reinterpret_cast<const float4*>(&nrow[2 * j]);
    float4 n1 = *reinterpret_cast<const float4*>(&nrow[2 * j + 4]);
    s.x += (fabsf(bp.x) + cG) * n0.x - (fabsf(bn.x) + cG) * n0.y;
    s.y += (fabsf(bp.y) + cG) * n0.z - (fabsf(bn.y) + cG) * n0.w;
    s.z += (fabsf(bp.z) + cG) * n1.x - (fabsf(bn.z) + cG) * n1.y;
    s.w += (fabsf(bp.w) + cG) * n1.z - (fabsf(bn.w) + cG) * n1.w;
    out[t] = s;
}

// ---------------------------------------------------------------------------
extern "C" void kernel_launch(void* const* d_in, const int* in_sizes, int n_in,
                              void* d_out, int out_size) {
    const float* x       = (const float*)d_in[0];
    const float* w_pos   = (const float*)d_in[1];
    const float* w_neg   = (const float*)d_in[2];
    const float* b_pos   = (const float*)d_in[3];
    const float* b_neg   = (const float*)d_in[4];
    const float* n_param = (const float*)d_in[5];

    k_max<<<256, 256>>>((const float4*)w_pos, (const float4*)w_neg);
    dim3 grid(NJT, NCH);                      // 16 x 37
    k_main<<<grid, 256>>>(x, w_pos, w_neg, n_param);
    k_reduce<<<256, 64>>>((float4*)d_out, b_pos, b_neg, n_param);
}

// round 6
// speedup vs baseline: 1.0462x; 1.0462x over previous
#include <cuda_runtime.h>

#define BATCH 128
#define NIN   1024
#define NOUT  512
#define JT    16
#define NJT   (NOUT / JT)    // 32
#define NCH   9              // 8 chunks of 114 + 1 of 112 ; grid 32*9=288 ~ 148*2
#define E0    2.1245f
#define LN2   0.69314718f

__device__ int   g_max_bits;                     // zero-init; monotone -> replay-stable
__device__ float g_lvT[NIN * BATCH];             // transposed clamped lg2 input (512 KB)
__device__ float g_partial[NCH * BATCH * NOUT];  // 2.36 MB

__device__ __forceinline__ float ex2f_(float x) {
    float y; asm("ex2.approx.f32 %0, %1;" : "=f"(y) : "f"(x)); return y;
}
__device__ __forceinline__ float lg2f_(float x) {
    float y; asm("lg2.approx.f32 %0, %1;" : "=f"(y) : "f"(x)); return y;
}

// ---------------------------------------------------------------------------
// Kernel 1: fused prep.
//  blocks 0..255  : max |w| scan (MLP=4), atomicMax on positive-float bits
//  blocks 256..383: lvT[i][b] = max(lg2(2*clip(x[b][i])), -8)
// ---------------------------------------------------------------------------
__global__ void __launch_bounds__(256)
k_prep(const float4* __restrict__ wp4, const float4* __restrict__ wn4,
       const float4* __restrict__ x4) {
    if (blockIdx.x < 256) {
        const int gid = blockIdx.x * 256 + threadIdx.x;    // 65536 threads
        float4 a0 = wp4[gid], a1 = wp4[gid + 65536];
        float4 b0 = wn4[gid], b1 = wn4[gid + 65536];
        float m = 0.5f;
        m = fmaxf(m, fmaxf(fmaxf(fabsf(a0.x), fabsf(a0.y)), fmaxf(fabsf(a0.z), fabsf(a0.w))));
        m = fmaxf(m, fmaxf(fmaxf(fabsf(a1.x), fabsf(a1.y)), fmaxf(fabsf(a1.z), fabsf(a1.w))));
        m = fmaxf(m, fmaxf(fmaxf(fabsf(b0.x), fabsf(b0.y)), fmaxf(fabsf(b0.z), fabsf(b0.w))));
        m = fmaxf(m, fmaxf(fmaxf(fabsf(b1.x), fabsf(b1.y)), fmaxf(fabsf(b1.z), fabsf(b1.w))));
        #pragma unroll
        for (int o = 16; o; o >>= 1) m = fmaxf(m, __shfl_xor_sync(0xffffffffu, m, o));
        __shared__ float sm[8];
        const int lane = threadIdx.x & 31, w = threadIdx.x >> 5;
        if (lane == 0) sm[w] = m;
        __syncthreads();
        if (threadIdx.x == 0) {
            #pragma unroll
            for (int i = 1; i < 8; i++) m = fmaxf(m, sm[i]);
            atomicMax(&g_max_bits, __float_as_int(m));
        }
    } else {
        const int t = (blockIdx.x - 256) * 256 + threadIdx.x;  // 0..32767
        float4 xv = x4[t];                                     // x[b][i..i+3]
        const int b = t >> 8;
        const int i = (t & 255) * 4;
        float l0 = fmaxf(lg2f_(2.0f * fminf(fmaxf(xv.x, 0.0f), 1.0f)), -8.0f);
        float l1 = fmaxf(lg2f_(2.0f * fminf(fmaxf(xv.y, 0.0f), 1.0f)), -8.0f);
        float l2 = fmaxf(lg2f_(2.0f * fminf(fmaxf(xv.z, 0.0f), 1.0f)), -8.0f);
        float l3 = fmaxf(lg2f_(2.0f * fminf(fmaxf(xv.w, 0.0f), 1.0f)), -8.0f);
        g_lvT[(i + 0) * BATCH + b] = l0;
        g_lvT[(i + 1) * BATCH + b] = l1;
        g_lvT[(i + 2) * BATCH + b] = l2;
        g_lvT[(i + 3) * BATCH + b] = l3;
    }
}

// ---------------------------------------------------------------------------
// Kernel 2: main compute — MUFU-free scalar-FFMA inner loop (Taylor K=4).
//   term = sum_{k<4} phi_k[b,i] * C_k[i,j]
//   phi_k = vr^E0 * (lv*ln2)^k / k!        (staged, 1 MUFU per (b,i))
//   C_k   = cp*eps_p^k - cn*eps_n^k        (staged)
// Block = 256 thr: 16 j-lanes x 16 batch-groups of 8. 4 FFMA per element.
// ---------------------------------------------------------------------------
#define SR 19     // rows per stage
__shared__ float  phi_s[SR * 4 * BATCH];   // 38912 B
__shared__ float4 coef_s[SR * JT];         //  4864 B

template<int ROWS>
__device__ __forceinline__ void stage_rows(
    const float* __restrict__ w_pos, const float* __restrict__ w_neg,
    const float* __restrict__ n_param,
    int i0, int j0, int tid, int jx, int bbase, float cG, float* acc)
{
    __syncthreads();
    // ---- stage phi[ii][k][b] (STS conflict-free: b fast)
    constexpr int TOT_LV = ROWS * BATCH;
    #pragma unroll
    for (int r = 0; r < (TOT_LV + 255) / 256; r++) {
        int idx = r * 256 + tid;
        if ((TOT_LV % 256 == 0) || idx < TOT_LV) {
            int ii = idx >> 7;
            int b  = idx & 127;
            float lv = g_lvT[(i0 + ii) * BATCH + b];     // coalesced
            float p0 = ex2f_(E0 * lv);
            float L  = lv * LN2;
            float p1 = p0 * L;
            float p2 = p1 * (L * 0.5f);
            float p3 = p2 * (L * 0.33333333f);
            float* dst = &phi_s[ii * (4 * BATCH) + b];
            dst[0]         = p0;
            dst[BATCH]     = p1;
            dst[2 * BATCH] = p2;
            dst[3 * BATCH] = p3;
        }
    }
    // ---- stage C_k[ii][jj]
    constexpr int TOT_CF = ROWS * JT;
    #pragma unroll
    for (int r = 0; r < (TOT_CF + 255) / 256; r++) {
        int idx = r * 256 + tid;
        if ((TOT_CF % 256 == 0) || idx < TOT_CF) {
            int ii = idx >> 4, jj = idx & 15;
            int i = i0 + ii, j = j0 + jj;
            float cp = 0.5f * (fabsf(w_pos[i * NOUT + j]) + cG);
            float cn = 0.5f * (fabsf(w_neg[i * NOUT + j]) + cG);
            float2 np = reinterpret_cast<const float2*>(n_param)[i * NOUT + j];
            float ep = lg2f_(np.x) + 1.0f - E0;
            float en = lg2f_(np.y) + 1.0f - E0;
            coef_s[idx] = make_float4(cp - cn,
                                      cp * ep - cn * en,
                                      cp * ep * ep - cn * en * en,
                                      cp * ep * ep * ep - cn * en * en * en);
        }
    }
    __syncthreads();

    // ---- inner loop: 32 scalar FFMA + 9 LDS per thread*ii (FFMA-bound)
    #pragma unroll 2
    for (int ii = 0; ii < ROWS; ii++) {
        const float4 C = coef_s[ii * JT + jx];
        const float* pb = &phi_s[ii * (4 * BATCH) + bbase];
        #pragma unroll
        for (int k = 0; k < 4; k++) {
            const float4* p4 = reinterpret_cast<const float4*>(pb + k * BATCH);
            float4 a = p4[0], b = p4[1];
            const float ck = (k == 0) ? C.x : (k == 1) ? C.y : (k == 2) ? C.z : C.w;
            acc[0] = fmaf(ck, a.x, acc[0]);
            acc[1] = fmaf(ck, a.y, acc[1]);
            acc[2] = fmaf(ck, a.z, acc[2]);
            acc[3] = fmaf(ck, a.w, acc[3]);
            acc[4] = fmaf(ck, b.x, acc[4]);
            acc[5] = fmaf(ck, b.y, acc[5]);
            acc[6] = fmaf(ck, b.z, acc[6]);
            acc[7] = fmaf(ck, b.w, acc[7]);
        }
    }
}

__global__ void __launch_bounds__(256)
k_main(const float* __restrict__ w_pos, const float* __restrict__ w_neg,
       const float* __restrict__ n_param) {
    const int tid   = threadIdx.x;
    const int jx    = tid & 15;
    const int bbase = (tid >> 4) * 8;
    const int j0    = blockIdx.x * JT;
    const int ch    = blockIdx.y;
    const int i0    = ch * 114;
    const float cG  = __int_as_float(g_max_bits) * (1.0f / 9.0f);

    float acc[8];
    #pragma unroll
    for (int p = 0; p < 8; p++) acc[p] = 0.0f;

    if (ch < 8) {     // 114 rows = 6 x 19
        #pragma unroll 1
        for (int s = 0; s < 6; s++)
            stage_rows<19>(w_pos, w_neg, n_param, i0 + s * 19, j0,
                           tid, jx, bbase, cG, acc);
    } else {          // 112 rows = 5 x 19 + 17
        #pragma unroll 1
        for (int s = 0; s < 5; s++)
            stage_rows<19>(w_pos, w_neg, n_param, i0 + s * 19, j0,
                           tid, jx, bbase, cG, acc);
        stage_rows<17>(w_pos, w_neg, n_param, i0 + 95, j0,
                       tid, jx, bbase, cG, acc);
    }

    float* outp = &g_partial[ch * (BATCH * NOUT)];
    #pragma unroll
    for (int p = 0; p < 8; p++)
        outp[(bbase + p) * NOUT + j0 + jx] = acc[p];
}

// ---------------------------------------------------------------------------
// Kernel 3: deterministic reduction over chunks + exact bias term
// (bias row: vr = 2 exactly -> vr^(lg2 n + 1) = 2n -> term = (|b|+cG)*n)
// ---------------------------------------------------------------------------
__global__ void __launch_bounds__(256)
k_reduce(float4* __restrict__ out,
         const float* __restrict__ b_pos,
         const float* __restrict__ b_neg,
         const float* __restrict__ n_param) {
    const int t = blockIdx.x * blockDim.x + threadIdx.x;   // 16384 threads
    const float4* gp = reinterpret_cast<const float4*>(g_partial);
    float4 s = make_float4(0.0f, 0.0f, 0.0f, 0.0f);
    #pragma unroll
    for (int c = 0; c < NCH; c++) {
        float4 v = gp[c * (BATCH * NOUT / 4) + t];
        s.x += v.x; s.y += v.y; s.z += v.z; s.w += v.w;
    }
    const int j = (t * 4) & (NOUT - 1);
    const float cG = __int_as_float(g_max_bits) * (1.0f / 9.0f);
    float4 bp = *reinterpret_cast<const float4*>(&b_pos[j]);
    float4 bn = *reinterpret_cast<const float4*>(&b_neg[j]);
    const float* nrow = n_param + (size_t)NIN * (2 * NOUT);
    float4 n0 = *reinterpret_cast<const float4*>(&nrow[2 * j]);
    float4 n1 = *reinterpret_cast<const float4*>(&nrow[2 * j + 4]);
    s.x += (fabsf(bp.x) + cG) * n0.x - (fabsf(bn.x) + cG) * n0.y;
    s.y += (fabsf(bp.y) + cG) * n0.z - (fabsf(bn.y) + cG) * n0.w;
    s.z += (fabsf(bp.z) + cG) * n1.x - (fabsf(bn.z) + cG) * n1.y;
    s.w += (fabsf(bp.w) + cG) * n1.z - (fabsf(bn.w) + cG) * n1.w;
    out[t] = s;
}

// ---------------------------------------------------------------------------
extern "C" void kernel_launch(void* const* d_in, const int* in_sizes, int n_in,
                              void* d_out, int out_size) {
    const float* x       = (const float*)d_in[0];
    const float* w_pos   = (const float*)d_in[1];
    const float* w_neg   = (const float*)d_in[2];
    const float* b_pos   = (const float*)d_in[3];
    const float* b_neg   = (const float*)d_in[4];
    const float* n_param = (const float*)d_in[5];

    k_prep<<<384, 256>>>((const float4*)w_pos, (const float4*)w_neg,
                         (const float4*)x);
    dim3 grid(NJT, NCH);                      // 32 x 9 = 288 ~ 148*2
    k_main<<<grid, 256>>>(w_pos, w_neg, n_param);
    k_reduce<<<64, 256>>>((float4*)d_out, b_pos, b_neg, n_param);
}

// round 7
// speedup vs baseline: 1.4701x; 1.4051x over previous
#include <cuda_runtime.h>

#define BATCH 128
#define NIN   1024
#define NOUT  512
#define JT    64
#define NJT   (NOUT / JT)    // 8
#define NCH   37             // 36 chunks of 28 + 1 of 16 ; grid 8*37 = 296 = 148*2
#define SRMAX 14
#define E0    2.1245f
#define LN2   0.69314718f

__device__ int   g_max_bits;                     // zero-init; monotone -> replay-stable
__device__ float g_lvT[NIN * BATCH];             // transposed clamped lg2 input (512 KB)
__device__ float g_partial[NCH * BATCH * NOUT];  // 9.7 MB

__device__ __forceinline__ float ex2f_(float x) {
    float y; asm("ex2.approx.f32 %0, %1;" : "=f"(y) : "f"(x)); return y;
}
__device__ __forceinline__ float lg2f_(float x) {
    float y; asm("lg2.approx.f32 %0, %1;" : "=f"(y) : "f"(x)); return y;
}

// ---------------------------------------------------------------------------
// Kernel 1: fused prep.
//  blocks 0..255  : max |w| scan (MLP=4), atomicMax on positive-float bits
//  blocks 256..383: lvT[i][b] = max(lg2(2*clip(x[b][i])), -8)
// ---------------------------------------------------------------------------
__global__ void __launch_bounds__(256)
k_prep(const float4* __restrict__ wp4, const float4* __restrict__ wn4,
       const float4* __restrict__ x4) {
    if (blockIdx.x < 256) {
        const int gid = blockIdx.x * 256 + threadIdx.x;    // 65536 threads
        float4 a0 = wp4[gid], a1 = wp4[gid + 65536];
        float4 b0 = wn4[gid], b1 = wn4[gid + 65536];
        float m = 0.5f;
        m = fmaxf(m, fmaxf(fmaxf(fabsf(a0.x), fabsf(a0.y)), fmaxf(fabsf(a0.z), fabsf(a0.w))));
        m = fmaxf(m, fmaxf(fmaxf(fabsf(a1.x), fabsf(a1.y)), fmaxf(fabsf(a1.z), fabsf(a1.w))));
        m = fmaxf(m, fmaxf(fmaxf(fabsf(b0.x), fabsf(b0.y)), fmaxf(fabsf(b0.z), fabsf(b0.w))));
        m = fmaxf(m, fmaxf(fmaxf(fabsf(b1.x), fabsf(b1.y)), fmaxf(fabsf(b1.z), fabsf(b1.w))));
        #pragma unroll
        for (int o = 16; o; o >>= 1) m = fmaxf(m, __shfl_xor_sync(0xffffffffu, m, o));
        __shared__ float sm[8];
        const int lane = threadIdx.x & 31, w = threadIdx.x >> 5;
        if (lane == 0) sm[w] = m;
        __syncthreads();
        if (threadIdx.x == 0) {
            #pragma unroll
            for (int i = 1; i < 8; i++) m = fmaxf(m, sm[i]);
            atomicMax(&g_max_bits, __float_as_int(m));
        }
    } else {
        const int t = (blockIdx.x - 256) * 256 + threadIdx.x;  // 0..32767
        float4 xv = x4[t];                                     // x[b][i..i+3]
        const int b = t >> 8;
        const int i = (t & 255) * 4;
        g_lvT[(i + 0) * BATCH + b] = fmaxf(lg2f_(2.0f * fminf(fmaxf(xv.x, 0.0f), 1.0f)), -8.0f);
        g_lvT[(i + 1) * BATCH + b] = fmaxf(lg2f_(2.0f * fminf(fmaxf(xv.y, 0.0f), 1.0f)), -8.0f);
        g_lvT[(i + 2) * BATCH + b] = fmaxf(lg2f_(2.0f * fminf(fmaxf(xv.z, 0.0f), 1.0f)), -8.0f);
        g_lvT[(i + 3) * BATCH + b] = fmaxf(lg2f_(2.0f * fminf(fmaxf(xv.w, 0.0f), 1.0f)), -8.0f);
    }
}

// ---------------------------------------------------------------------------
// Kernel 2: main compute. Taylor K=4, register-blocked 4j x 8b per thread.
//   term = sum_{k<4} phi_k[b,i] * C_k[i,j]
// Per thread*ii: 12 LDS.128 for 32 elements (LDS 48 cyc/warp*ii)
//                128 FFMA (64 SM-cyc/warp*ii)  -> FFMA-bound.
// Block: 256 thr = 16 j-quads x 16 batch-octets covering 64j x 128b.
// ---------------------------------------------------------------------------
template<int SR>
__device__ __forceinline__ void stage_rows(
    const float* __restrict__ w_pos, const float* __restrict__ w_neg,
    const float* __restrict__ n_param,
    float* phi_s, float* coef_s,
    int i0, int j0, int tid, int jq, int bbase, float cG, float (*acc)[8])
{
    __syncthreads();
    // ---- stage phi[ii][k][b]  (conflict-free STS, coalesced LDG)
    constexpr int TOT_LV = SR * BATCH;
    #pragma unroll
    for (int r = 0; r < (TOT_LV + 255) / 256; r++) {
        int idx = r * 256 + tid;
        if ((TOT_LV % 256 == 0) || idx < TOT_LV) {
            int ii = idx >> 7;
            int b  = idx & 127;
            float lv = g_lvT[(i0 + ii) * BATCH + b];
            float p0 = ex2f_(E0 * lv);
            float L  = lv * LN2;
            float p1 = p0 * L;
            float p2 = p1 * (L * 0.5f);
            float p3 = p2 * (L * 0.33333333f);
            float* dst = &phi_s[ii * 512 + b];
            dst[0]   = p0;
            dst[128] = p1;
            dst[256] = p2;
            dst[384] = p3;
        }
    }
    // ---- stage C_k at coef[ii][k][j]  (transposed: one LDS.128 per k-step)
    constexpr int TOT_CF = SR * JT;
    #pragma unroll
    for (int r = 0; r < (TOT_CF + 255) / 256; r++) {
        int idx = r * 256 + tid;
        if ((TOT_CF % 256 == 0) || idx < TOT_CF) {
            int ii = idx >> 6, jj = idx & 63;
            int i = i0 + ii, j = j0 + jj;
            float cp = 0.5f * (fabsf(w_pos[i * NOUT + j]) + cG);
            float cn = 0.5f * (fabsf(w_neg[i * NOUT + j]) + cG);
            float2 np = reinterpret_cast<const float2*>(n_param)[i * NOUT + j];
            float ep = lg2f_(np.x) + 1.0f - E0;
            float en = lg2f_(np.y) + 1.0f - E0;
            float* dst = &coef_s[ii * 256 + jj];
            dst[0]   = cp - cn;
            dst[64]  = cp * ep - cn * en;
            dst[128] = cp * ep * ep - cn * en * en;
            dst[192] = cp * ep * ep * ep - cn * en * en * en;
        }
    }
    __syncthreads();

    // ---- inner loop
    #pragma unroll 2
    for (int ii = 0; ii < SR; ii++) {
        const float* cb = &coef_s[ii * 256 + jq * 4];
        const float* pb = &phi_s[ii * 512 + bbase];
        #pragma unroll
        for (int k = 0; k < 4; k++) {
            float4 c  = *reinterpret_cast<const float4*>(cb + k * 64);
            float4 pa = *reinterpret_cast<const float4*>(pb + k * 128);
            float4 pc = *reinterpret_cast<const float4*>(pb + k * 128 + 4);
            const float cv[4] = {c.x, c.y, c.z, c.w};
            const float pv[8] = {pa.x, pa.y, pa.z, pa.w, pc.x, pc.y, pc.z, pc.w};
            #pragma unroll
            for (int j = 0; j < 4; j++)
                #pragma unroll
                for (int b = 0; b < 8; b++)
                    acc[j][b] = fmaf(cv[j], pv[b], acc[j][b]);
        }
    }
}

__global__ void __launch_bounds__(256)
k_main(const float* __restrict__ w_pos, const float* __restrict__ w_neg,
       const float* __restrict__ n_param) {
    __shared__ __align__(16) float phi_s[SRMAX * 4 * BATCH];   // 28 KB
    __shared__ __align__(16) float coef_s[SRMAX * 4 * JT];     // 14 KB

    const int tid   = threadIdx.x;
    const int jq    = tid & 15;          // j-quad: 4 consecutive j
    const int bbase = (tid >> 4) * 8;    // batch octet
    const int j0    = blockIdx.x * JT;
    const int ch    = blockIdx.y;
    const float cG  = __int_as_float(g_max_bits) * (1.0f / 9.0f);

    float acc[4][8];
    #pragma unroll
    for (int j = 0; j < 4; j++)
        #pragma unroll
        for (int b = 0; b < 8; b++) acc[j][b] = 0.0f;

    if (ch < 36) {
        int i0 = ch * 28;
        stage_rows<14>(w_pos, w_neg, n_param, phi_s, coef_s, i0,      j0, tid, jq, bbase, cG, acc);
        stage_rows<14>(w_pos, w_neg, n_param, phi_s, coef_s, i0 + 14, j0, tid, jq, bbase, cG, acc);
    } else {
        stage_rows<8>(w_pos, w_neg, n_param, phi_s, coef_s, 1008, j0, tid, jq, bbase, cG, acc);
        stage_rows<8>(w_pos, w_neg, n_param, phi_s, coef_s, 1016, j0, tid, jq, bbase, cG, acc);
    }

    float* outp = &g_partial[ch * (BATCH * NOUT)];
    #pragma unroll
    for (int b = 0; b < 8; b++) {
        float4 v = make_float4(acc[0][b], acc[1][b], acc[2][b], acc[3][b]);
        *reinterpret_cast<float4*>(&outp[(bbase + b) * NOUT + j0 + jq * 4]) = v;
    }
}

// ---------------------------------------------------------------------------
// Kernel 3: deterministic reduction over chunks + exact bias term
// (bias row: vr = 2 exactly -> vr^(lg2 n + 1) = 2n -> term = (|b|+cG)*n)
// ---------------------------------------------------------------------------
__global__ void __launch_bounds__(256)
k_reduce(float4* __restrict__ out,
         const float* __restrict__ b_pos,
         const float* __restrict__ b_neg,
         const float* __restrict__ n_param) {
    const int t = blockIdx.x * blockDim.x + threadIdx.x;   // 16384 threads
    const float4* gp = reinterpret_cast<const float4*>(g_partial);
    float4 s = make_float4(0.0f, 0.0f, 0.0f, 0.0f);
    #pragma unroll
    for (int c = 0; c < NCH; c++) {
        float4 v = gp[c * (BATCH * NOUT / 4) + t];
        s.x += v.x; s.y += v.y; s.z += v.z; s.w += v.w;
    }
    const int j = (t * 4) & (NOUT - 1);
    const float cG = __int_as_float(g_max_bits) * (1.0f / 9.0f);
    float4 bp = *reinterpret_cast<const float4*>(&b_pos[j]);
    float4 bn = *reinterpret_cast<const float4*>(&b_neg[j]);
    const float* nrow = n_param + (size_t)NIN * (2 * NOUT);
    float4 n0 = *reinterpret_cast<const float4*>(&nrow[2 * j]);
    float4 n1 = *reinterpret_cast<const float4*>(&nrow[2 * j + 4]);
    s.x += (fabsf(bp.x) + cG) * n0.x - (fabsf(bn.x) + cG) * n0.y;
    s.y += (fabsf(bp.y) + cG) * n0.z - (fabsf(bn.y) + cG) * n0.w;
    s.z += (fabsf(bp.z) + cG) * n1.x - (fabsf(bn.z) + cG) * n1.y;
    s.w += (fabsf(bp.w) + cG) * n1.z - (fabsf(bn.w) + cG) * n1.w;
    out[t] = s;
}

// ---------------------------------------------------------------------------
extern "C" void kernel_launch(void* const* d_in, const int* in_sizes, int n_in,
                              void* d_out, int out_size) {
    const float* x       = (const float*)d_in[0];
    const float* w_pos   = (const float*)d_in[1];
    const float* w_neg   = (const float*)d_in[2];
    const float* b_pos   = (const float*)d_in[3];
    const float* b_neg   = (const float*)d_in[4];
    const float* n_param = (const float*)d_in[5];

    k_prep<<<384, 256>>>((const float4*)w_pos, (const float4*)w_neg,
                         (const float4*)x);
    dim3 grid(NJT, NCH);                      // 8 x 37 = 296 = 148*2
    k_main<<<grid, 256>>>(w_pos, w_neg, n_param);
    k_reduce<<<64, 256>>>((float4*)d_out, b_pos, b_neg, n_param);
}

// round 8
// speedup vs baseline: 1.4738x; 1.0026x over previous
#include <cuda_runtime.h>

#define BATCH 128
#define NIN   1024
#define NOUT  512
#define JT    64
#define NJT   (NOUT / JT)    // 8
#define NCH   37             // 36 chunks of 28 + 1 of 16 ; grid 8*37 = 296 = 148*2
#define NBLK  296
#define NTHR  (NBLK * 256)   // 75776
#define SRMAX 14
#define E0    2.1245f
#define LN2   0.69314718f
#define W_F4  131072         // float4 count per w array
#define X_F4  32768          // float4 count of x

__device__ int          g_max_bits;              // zero-init; monotone -> replay-stable
__device__ unsigned int g_gate;                  // arrival counter; reset by k_reduce
__device__ float        g_lvT[NIN * BATCH];      // transposed clamped lg2 input
__device__ float        g_partial[NCH * BATCH * NOUT];

__device__ __forceinline__ float ex2f_(float x) {
    float y; asm("ex2.approx.f32 %0, %1;" : "=f"(y) : "f"(x)); return y;
}
__device__ __forceinline__ float lg2f_(float x) {
    float y; asm("lg2.approx.f32 %0, %1;" : "=f"(y) : "f"(x)); return y;
}

// ---------------------------------------------------------------------------
// Main kernel with cooperative prologue (all 296 CTAs co-resident at occ=2).
// Prologue: slice-scan max|w|, slice-build lvT, then global gate.
// Body: Taylor K=4, register-blocked 4j x 8b per thread (FFMA-bound).
// ---------------------------------------------------------------------------
template<int SR>
__device__ __forceinline__ void stage_rows(
    const float* __restrict__ w_pos, const float* __restrict__ w_neg,
    const float* __restrict__ n_param,
    float* phi_s, float* coef_s,
    int i0, int j0, int tid, int jq, int bbase, float cG, float (*acc)[8])
{
    __syncthreads();
    // ---- stage phi[ii][k][b]
    constexpr int TOT_LV = SR * BATCH;
    #pragma unroll
    for (int r = 0; r < (TOT_LV + 255) / 256; r++) {
        int idx = r * 256 + tid;
        if ((TOT_LV % 256 == 0) || idx < TOT_LV) {
            int ii = idx >> 7;
            int b  = idx & 127;
            float lv = g_lvT[(i0 + ii) * BATCH + b];
            float p0 = ex2f_(E0 * lv);
            float L  = lv * LN2;
            float p1 = p0 * L;
            float p2 = p1 * (L * 0.5f);
            float p3 = p2 * (L * 0.33333333f);
            float* dst = &phi_s[ii * 512 + b];
            dst[0]   = p0;
            dst[128] = p1;
            dst[256] = p2;
            dst[384] = p3;
        }
    }
    // ---- stage C_k at coef[ii][k][j]
    constexpr int TOT_CF = SR * JT;
    #pragma unroll
    for (int r = 0; r < (TOT_CF + 255) / 256; r++) {
        int idx = r * 256 + tid;
        if ((TOT_CF % 256 == 0) || idx < TOT_CF) {
            int ii = idx >> 6, jj = idx & 63;
            int i = i0 + ii, j = j0 + jj;
            float cp = 0.5f * (fabsf(w_pos[i * NOUT + j]) + cG);
            float cn = 0.5f * (fabsf(w_neg[i * NOUT + j]) + cG);
            float2 np = reinterpret_cast<const float2*>(n_param)[i * NOUT + j];
            float ep = lg2f_(np.x) + 1.0f - E0;
            float en = lg2f_(np.y) + 1.0f - E0;
            float* dst = &coef_s[ii * 256 + jj];
            dst[0]   = cp - cn;
            dst[64]  = cp * ep - cn * en;
            dst[128] = cp * ep * ep - cn * en * en;
            dst[192] = cp * ep * ep * ep - cn * en * en * en;
        }
    }
    __syncthreads();

    // ---- inner loop: 12 LDS.128 / 128 FFMA per thread*ii -> FFMA-bound
    #pragma unroll 2
    for (int ii = 0; ii < SR; ii++) {
        const float* cb = &coef_s[ii * 256 + jq * 4];
        const float* pb = &phi_s[ii * 512 + bbase];
        #pragma unroll
        for (int k = 0; k < 4; k++) {
            float4 c  = *reinterpret_cast<const float4*>(cb + k * 64);
            float4 pa = *reinterpret_cast<const float4*>(pb + k * 128);
            float4 pc = *reinterpret_cast<const float4*>(pb + k * 128 + 4);
            const float cv[4] = {c.x, c.y, c.z, c.w};
            const float pv[8] = {pa.x, pa.y, pa.z, pa.w, pc.x, pc.y, pc.z, pc.w};
            #pragma unroll
            for (int j = 0; j < 4; j++)
                #pragma unroll
                for (int b = 0; b < 8; b++)
                    acc[j][b] = fmaf(cv[j], pv[b], acc[j][b]);
        }
    }
}

__global__ void __launch_bounds__(256, 2)
k_main(const float4* __restrict__ x4,
       const float* __restrict__ w_pos, const float* __restrict__ w_neg,
       const float* __restrict__ n_param) {
    __shared__ __align__(16) float phi_s[SRMAX * 4 * BATCH];   // 28 KB
    __shared__ __align__(16) float coef_s[SRMAX * 4 * JT];     // 14 KB

    const int tid = threadIdx.x;
    const int bid = blockIdx.y * NJT + blockIdx.x;
    const int g   = bid * 256 + tid;

    // ================= cooperative prologue =================
    // 1) slice of max|w| scan
    const float4* wp4 = reinterpret_cast<const float4*>(w_pos);
    const float4* wn4 = reinterpret_cast<const float4*>(w_neg);
    float m = 0.5f;   // bias value always present
    for (int idx = g; idx < 2 * W_F4; idx += NTHR) {
        float4 a = (idx < W_F4) ? wp4[idx] : wn4[idx - W_F4];
        m = fmaxf(m, fmaxf(fmaxf(fabsf(a.x), fabsf(a.y)),
                           fmaxf(fabsf(a.z), fabsf(a.w))));
    }
    // 2) slice of lvT transpose
    for (int idx = g; idx < X_F4; idx += NTHR) {
        float4 xv = x4[idx];
        int b = idx >> 8;
        int i = (idx & 255) * 4;
        g_lvT[(i + 0) * BATCH + b] = fmaxf(lg2f_(2.0f * fminf(fmaxf(xv.x, 0.0f), 1.0f)), -8.0f);
        g_lvT[(i + 1) * BATCH + b] = fmaxf(lg2f_(2.0f * fminf(fmaxf(xv.y, 0.0f), 1.0f)), -8.0f);
        g_lvT[(i + 2) * BATCH + b] = fmaxf(lg2f_(2.0f * fminf(fmaxf(xv.z, 0.0f), 1.0f)), -8.0f);
        g_lvT[(i + 3) * BATCH + b] = fmaxf(lg2f_(2.0f * fminf(fmaxf(xv.w, 0.0f), 1.0f)), -8.0f);
    }
    // 3) block-reduce max, publish, arrive on gate
    #pragma unroll
    for (int o = 16; o; o >>= 1) m = fmaxf(m, __shfl_xor_sync(0xffffffffu, m, o));
    {
        float* sm = coef_s;   // reuse before staging
        const int lane = tid & 31, w = tid >> 5;
        if (lane == 0) sm[w] = m;
        __syncthreads();
        if (tid == 0) {
            #pragma unroll
            for (int i = 1; i < 8; i++) m = fmaxf(m, sm[i]);
            atomicMax(&g_max_bits, __float_as_int(m));
            __threadfence();
            atomicAdd(&g_gate, 1u);
            // 4) spin until all 296 CTAs arrived (all co-resident -> safe)
            while (*reinterpret_cast<volatile unsigned int*>(&g_gate) < NBLK)
                __nanosleep(32);
        }
    }
    __syncthreads();
    __threadfence();
    // ================= end prologue =================

    const int jq    = tid & 15;
    const int bbase = (tid >> 4) * 8;
    const int j0    = blockIdx.x * JT;
    const int ch    = blockIdx.y;
    const float cG  = __int_as_float(g_max_bits) * (1.0f / 9.0f);

    float acc[4][8];
    #pragma unroll
    for (int j = 0; j < 4; j++)
        #pragma unroll
        for (int b = 0; b < 8; b++) acc[j][b] = 0.0f;

    if (ch < 36) {
        int i0 = ch * 28;
        stage_rows<14>(w_pos, w_neg, n_param, phi_s, coef_s, i0,      j0, tid, jq, bbase, cG, acc);
        stage_rows<14>(w_pos, w_neg, n_param, phi_s, coef_s, i0 + 14, j0, tid, jq, bbase, cG, acc);
    } else {
        stage_rows<8>(w_pos, w_neg, n_param, phi_s, coef_s, 1008, j0, tid, jq, bbase, cG, acc);
        stage_rows<8>(w_pos, w_neg, n_param, phi_s, coef_s, 1016, j0, tid, jq, bbase, cG, acc);
    }

    float* outp = &g_partial[ch * (BATCH * NOUT)];
    #pragma unroll
    for (int b = 0; b < 8; b++) {
        float4 v = make_float4(acc[0][b], acc[1][b], acc[2][b], acc[3][b]);
        *reinterpret_cast<float4*>(&outp[(bbase + b) * NOUT + j0 + jq * 4]) = v;
    }
}

// ---------------------------------------------------------------------------
// Reduction over chunks + exact bias term; also resets the gate for replay.
// (bias row: vr = 2 exactly -> vr^(lg2 n + 1) = 2n -> term = (|b|+cG)*n)
// ---------------------------------------------------------------------------
__global__ void __launch_bounds__(256)
k_reduce(float4* __restrict__ out,
         const float* __restrict__ b_pos,
         const float* __restrict__ b_neg,
         const float* __restrict__ n_param) {
    const int t = blockIdx.x * blockDim.x + threadIdx.x;   // 16384 threads
    if (t == 0) g_gate = 0;                                 // replay reset
    const float4* gp = reinterpret_cast<const float4*>(g_partial);
    float4 s = make_float4(0.0f, 0.0f, 0.0f, 0.0f);
    #pragma unroll
    for (int c = 0; c < NCH; c++) {
        float4 v = gp[c * (BATCH * NOUT / 4) + t];
        s.x += v.x; s.y += v.y; s.z += v.z; s.w += v.w;
    }
    const int j = (t * 4) & (NOUT - 1);
    const float cG = __int_as_float(g_max_bits) * (1.0f / 9.0f);
    float4 bp = *reinterpret_cast<const float4*>(&b_pos[j]);
    float4 bn = *reinterpret_cast<const float4*>(&b_neg[j]);
    const float* nrow = n_param + (size_t)NIN * (2 * NOUT);
    float4 n0 = *reinterpret_cast<const float4*>(&nrow[2 * j]);
    float4 n1 = *reinterpret_cast<const float4*>(&nrow[2 * j + 4]);
    s.x += (fabsf(bp.x) + cG) * n0.x - (fabsf(bn.x) + cG) * n0.y;
    s.y += (fabsf(bp.y) + cG) * n0.z - (fabsf(bn.y) + cG) * n0.w;
    s.z += (fabsf(bp.z) + cG) * n1.x - (fabsf(bn.z) + cG) * n1.y;
    s.w += (fabsf(bp.w) + cG) * n1.z - (fabsf(bn.w) + cG) * n1.w;
    out[t] = s;
}

// ---------------------------------------------------------------------------
extern "C" void kernel_launch(void* const* d_in, const int* in_sizes, int n_in,
                              void* d_out, int out_size) {
    const float* x       = (const float*)d_in[0];
    const float* w_pos   = (const float*)d_in[1];
    const float* w_neg   = (const float*)d_in[2];
    const float* b_pos   = (const float*)d_in[3];
    const float* b_neg   = (const float*)d_in[4];
    const float* n_param = (const float*)d_in[5];

    dim3 grid(NJT, NCH);                      // 8 x 37 = 296 = 148*2 (all co-resident)
    k_main<<<grid, 256>>>((const float4*)x, w_pos, w_neg, n_param);
    k_reduce<<<64, 256>>>((float4*)d_out, b_pos, b_neg, n_param);
}